// round 3
// baseline (speedup 1.0000x reference)
#include <cuda_runtime.h>

#define G_TOTAL 32768
#define H1      150
#define PP      8

using u64 = unsigned long long;

// ---- packed f32x2 helpers (Blackwell sm_103a) ------------------------------
__device__ __forceinline__ u64 pk2(float a, float b) {
    u64 r;
    asm("mov.b64 %0,{%1,%2};" : "=l"(r)
        : "r"(__float_as_uint(a)), "r"(__float_as_uint(b)));
    return r;
}
__device__ __forceinline__ float2 upk2(u64 v) {
    unsigned lo, hi;
    asm("mov.b64 {%0,%1},%2;" : "=r"(lo), "=r"(hi) : "l"(v));
    return make_float2(__uint_as_float(lo), __uint_as_float(hi));
}
__device__ __forceinline__ u64 fma2(u64 a, u64 b, u64 c) {
    u64 d;
    asm("fma.rn.f32x2 %0,%1,%2,%3;" : "=l"(d) : "l"(a), "l"(b), "l"(c));
    return d;
}

// ---- shared-memory layout (floats) -----------------------------------------
// W1d : [150][40]  duplicated-transposed W1 rows ({w,w} pairs, padded to 40)
// W2d : [150][16]  duplicated W2 rows
// W3t : [150][40]  transposed W3 rows
#define SM_W1D 0
#define SM_W2D 6000
#define SM_W3T 8400
#define SM_B1  14400
#define SM_B3  14552
#define SM_W4  14704
#define SM_B2  14856
#define SM_FLOATS 14864
#define SM_BYTES  (SM_FLOATS * 4)

// ---- per-group tail: warp stats over 32 lanes + group MLP ------------------
__device__ __noinline__ float group_tail(const float* a,
                                         const float* __restrict__ W3t,
                                         const float* __restrict__ b3s,
                                         const float* __restrict__ W4s,
                                         float b4v, int lane)
{
    u64 ag[20];   // packed agg pairs: ag[stat*4 + p/2] = {agg_p, agg_p+1}

    #pragma unroll
    for (int ph = 0; ph < 4; ++ph) {
        float va = a[2 * ph], vb = a[2 * ph + 1];

        // mean
        float sa = va, sb = vb;
        #pragma unroll
        for (int o = 16; o; o >>= 1) {
            sa += __shfl_xor_sync(0xffffffffu, sa, o);
            sb += __shfl_xor_sync(0xffffffffu, sb, o);
        }
        float meana = sa * (1.0f / 32.0f), meanb = sb * (1.0f / 32.0f);

        // unbiased variance (two-pass)
        float da = va - meana, db = vb - meanb;
        float qa = da * da, qb = db * db;
        #pragma unroll
        for (int o = 16; o; o >>= 1) {
            qa += __shfl_xor_sync(0xffffffffu, qa, o);
            qb += __shfl_xor_sync(0xffffffffu, qb, o);
        }
        float vara = qa * (1.0f / 31.0f), varb = qb * (1.0f / 31.0f);

        // min / max
        float mna = va, mxa = va, mnb = vb, mxb = vb;
        #pragma unroll
        for (int o = 16; o; o >>= 1) {
            mna = fminf(mna, __shfl_xor_sync(0xffffffffu, mna, o));
            mxa = fmaxf(mxa, __shfl_xor_sync(0xffffffffu, mxa, o));
            mnb = fminf(mnb, __shfl_xor_sync(0xffffffffu, mnb, o));
            mxb = fmaxf(mxb, __shfl_xor_sync(0xffffffffu, mxb, o));
        }

        // lower median via warp bitonic sort (two sorts interleaved)
        float ta = va, tb = vb;
        #pragma unroll
        for (int k = 2; k <= 32; k <<= 1) {
            #pragma unroll
            for (int j = k >> 1; j > 0; j >>= 1) {
                float oa = __shfl_xor_sync(0xffffffffu, ta, j);
                float ob = __shfl_xor_sync(0xffffffffu, tb, j);
                bool keep_lo = (((lane & j) == 0) == ((lane & k) == 0));
                float la = fminf(ta, oa), ha = fmaxf(ta, oa);
                float lb = fminf(tb, ob), hb = fmaxf(tb, ob);
                ta = keep_lo ? la : ha;
                tb = keep_lo ? lb : hb;
            }
        }
        float meda = __shfl_sync(0xffffffffu, ta, 15);
        float medb = __shfl_sync(0xffffffffu, tb, 15);

        ag[0 * 4 + ph] = pk2(meana, meanb);
        ag[1 * 4 + ph] = pk2(vara, varb);
        ag[2 * 4 + ph] = pk2(mna, mnb);
        ag[3 * 4 + ph] = pk2(meda, medb);
        ag[4 * 4 + ph] = pk2(mxa, mxb);
    }

    // group MLP: 40 -> 150 (relu) -> 1, hidden units strided over lanes
    float zp = 0.0f;
    #pragma unroll 1
    for (int j = lane; j < H1; j += 32) {
        const ulonglong2* wr = (const ulonglong2*)(W3t + j * 40);
        u64 t2a = 0ull, t2b = 0ull;
        #pragma unroll
        for (int q = 0; q < 10; ++q) {
            ulonglong2 w = wr[q];
            t2a = fma2(ag[2 * q],     w.x, t2a);
            t2b = fma2(ag[2 * q + 1], w.y, t2b);
        }
        float2 sa = upk2(t2a), sb = upk2(t2b);
        float t = (sa.x + sa.y) + (sb.x + sb.y) + b3s[j];
        t = fmaxf(t, 0.0f);
        zp = fmaf(t, W4s[j], zp);
    }
    #pragma unroll
    for (int o = 16; o; o >>= 1) zp += __shfl_xor_sync(0xffffffffu, zp, o);

    return 1.0f / (1.0f + __expf(-(zp + b4v)));
}

__global__ void __launch_bounds__(256, 2)
minn_fused_v3_kernel(const float* __restrict__ x,
                     const int*   __restrict__ kmer,
                     const int*   __restrict__ indices,
                     const float* __restrict__ emb,
                     const float* __restrict__ W1, const float* __restrict__ b1,
                     const float* __restrict__ W2, const float* __restrict__ b2,
                     const float* __restrict__ W3, const float* __restrict__ b3,
                     const float* __restrict__ W4, const float* __restrict__ b4,
                     float* __restrict__ out)
{
    extern __shared__ float sm[];
    float* W1d = sm + SM_W1D;
    float* W2d = sm + SM_W2D;
    float* W3t = sm + SM_W3T;
    float* b1s = sm + SM_B1;
    float* b3s = sm + SM_B3;
    float* W4s = sm + SM_W4;
    float* b2s = sm + SM_B2;

    const int tid = threadIdx.x;

    // ---- stage weights: duplicate + transpose for vector broadcast loads ----
    for (int i = tid; i < H1 * 18; i += 256) {
        int j = i / 18, k = i - j * 18;
        float w = W1[k * H1 + j];
        W1d[j * 40 + 2 * k]     = w;
        W1d[j * 40 + 2 * k + 1] = w;
    }
    for (int i = tid; i < H1 * PP; i += 256) {
        int j = i >> 3, p = i & 7;
        float w = W2[i];
        W2d[j * 16 + 2 * p]     = w;
        W2d[j * 16 + 2 * p + 1] = w;
    }
    for (int i = tid; i < 40 * H1; i += 256) {
        int j = i / 40, k = i - j * 40;
        W3t[i] = W3[k * H1 + j];
    }
    for (int i = tid; i < H1; i += 256) {
        b1s[i] = b1[i];
        b3s[i] = b3[i];
        W4s[i] = W4[i];
    }
    if (tid < PP) b2s[tid] = b2[tid];
    const float b4v = __ldg(b4);
    __syncthreads();

    const int warp = tid >> 5;
    const int lane = tid & 31;
    const int g0 = (blockIdx.x * 8 + warp) * 2;   // 2 groups per warp

    // ---- gather the 2 reads this lane owns as one packed f32x2 stream ----
    const int r0 = indices[(g0 + 0) * 32 + lane];
    const int r1 = indices[(g0 + 1) * 32 + lane];

    u64 in[18];   // {read of group g0, read of group g0+1}
    {
        const float4* p0 = (const float4*)(x + (size_t)r0 * 16);
        const float4* p1 = (const float4*)(x + (size_t)r1 * 16);
        #pragma unroll
        for (int q = 0; q < 4; ++q) {
            float4 v0 = p0[q], v1 = p1[q];
            in[4 * q + 0] = pk2(v0.x, v1.x);
            in[4 * q + 1] = pk2(v0.y, v1.y);
            in[4 * q + 2] = pk2(v0.z, v1.z);
            in[4 * q + 3] = pk2(v0.w, v1.w);
        }
        float2 e0 = ((const float2*)emb)[kmer[r0]];
        float2 e1 = ((const float2*)emb)[kmer[r1]];
        in[16] = pk2(e0.x, e1.x);
        in[17] = pk2(e0.y, e1.y);
    }

    // ---- per-read MLP 18->150(relu)->8(relu), packed f32x2 ----
    u64 acc[PP];
    #pragma unroll
    for (int p = 0; p < PP; ++p) {
        float bp = b2s[p];
        acc[p] = pk2(bp, bp);
    }

    #pragma unroll 2
    for (int j = 0; j < H1; ++j) {
        float bj = b1s[j];
        // two independent accumulation chains for ILP
        u64 h0 = pk2(bj, bj), h1 = 0ull;
        const ulonglong2* w1r = (const ulonglong2*)(W1d + j * 40);
        #pragma unroll
        for (int q = 0; q < 4; ++q) {
            ulonglong2 wa = w1r[2 * q];
            ulonglong2 wb = w1r[2 * q + 1];
            h0 = fma2(in[4 * q + 0], wa.x, h0);
            h1 = fma2(in[4 * q + 1], wa.y, h1);
            h0 = fma2(in[4 * q + 2], wb.x, h0);
            h1 = fma2(in[4 * q + 3], wb.y, h1);
        }
        {
            ulonglong2 wc = w1r[8];
            h0 = fma2(in[16], wc.x, h0);
            h1 = fma2(in[17], wc.y, h1);
        }
        float2 r0v = upk2(h0), r1v = upk2(h1);
        float hx = fmaxf(r0v.x + r1v.x, 0.0f);
        float hy = fmaxf(r0v.y + r1v.y, 0.0f);
        u64 h = pk2(hx, hy);

        const ulonglong2* w2r = (const ulonglong2*)(W2d + j * 16);
        #pragma unroll
        for (int q = 0; q < 4; ++q) {
            ulonglong2 w = w2r[q];
            acc[2 * q]     = fma2(h, w.x, acc[2 * q]);
            acc[2 * q + 1] = fma2(h, w.y, acc[2 * q + 1]);
        }
    }

    // unpack per-group activations (+final relu)
    float s0[PP], s1[PP];
    #pragma unroll
    for (int p = 0; p < PP; ++p) {
        float2 t = upk2(acc[p]);
        s0[p] = fmaxf(t.x, 0.0f);
        s1[p] = fmaxf(t.y, 0.0f);
    }

    // ---- per-group aggregation + group MLP ----
    float o0 = group_tail(s0, W3t, b3s, W4s, b4v, lane);
    if (lane == 0) out[g0 + 0] = o0;
    float o1 = group_tail(s1, W3t, b3s, W4s, b4v, lane);
    if (lane == 0) out[g0 + 1] = o1;
}

extern "C" void kernel_launch(void* const* d_in, const int* in_sizes, int n_in,
                              void* d_out, int out_size)
{
    const float* x       = (const float*)d_in[0];
    const int*   kmer    = (const int*)  d_in[1];
    const int*   indices = (const int*)  d_in[2];
    const float* emb     = (const float*)d_in[3];
    const float* W1      = (const float*)d_in[4];
    const float* b1      = (const float*)d_in[5];
    const float* W2      = (const float*)d_in[6];
    const float* b2      = (const float*)d_in[7];
    const float* W3      = (const float*)d_in[8];
    const float* b3      = (const float*)d_in[9];
    const float* W4      = (const float*)d_in[10];
    const float* b4      = (const float*)d_in[11];
    float* out = (float*)d_out;

    cudaFuncSetAttribute(minn_fused_v3_kernel,
                         cudaFuncAttributeMaxDynamicSharedMemorySize, SM_BYTES);

    // 8 warps/block * 2 groups/warp = 16 groups per block
    const int blocks = G_TOTAL / 16;   // 2048
    minn_fused_v3_kernel<<<blocks, 256, SM_BYTES>>>(
        x, kmer, indices, emb, W1, b1, W2, b2, W3, b3, W4, b4, out);
}